// round 5
// baseline (speedup 1.0000x reference)
#include <cuda_runtime.h>
#include <math.h>

// ---------------------------------------------------------------------------
// LayerNormLSTM (2-layer bidirectional, with the reference's aliasing bug that
// makes layer-1's input time-constant).  B=64, S=48, E=H=512, G=4H=2048.
// Pure fp32 baseline: multi-kernel graph, sequential scan as 2 kernels/step.
// ---------------------------------------------------------------------------

namespace {
constexpr int Bz = 64;
constexpr int Sz = 48;
constexpr int Ez = 512;
constexpr int Hz = 512;
constexpr int Gz = 2048;   // 4H
constexpr float EPS = 1e-5f;
}

// ------------------------- static device scratch ---------------------------
__device__ float g_xT[Sz * Bz][Ez];          // x transposed to [s*B+b][e]  (6.3 MB)
__device__ float g_G0[2][Sz][Bz][Gz];        // layer0 LN(x @ W_ih^T)       (50 MB)
__device__ float g_G1[2][Bz][Gz];            // layer1 constant LN input    (1 MB)
__device__ float g_Yp[2][2][Bz][Gz];         // [ksplit][dir] GEMM partials (2 MB)
__device__ float g_h[2][Bz][Hz];             // hidden state per direction
__device__ float g_c[2][Bz][Hz];             // cell state per direction
__device__ float g_xc[Bz][2 * Hz];           // concat(hf, hb)

// ------------------------- small utility kernels ---------------------------
__global__ void zero_hc() {
    int i = blockIdx.x * blockDim.x + threadIdx.x;   // 256*256 = 65536 = 2*B*H
    (&g_h[0][0][0])[i] = 0.f;
    (&g_c[0][0][0])[i] = 0.f;
}

__global__ void transpose_x(const float* __restrict__ x) {
    int n = blockIdx.x;                   // n = s*B + b
    int s = n >> 6, b = n & 63;
    const float4* src = (const float4*)(x + ((size_t)b * Sz + s) * Ez);
    float4* dst = (float4*)g_xT[n];
    for (int i = threadIdx.x; i < Ez / 4; i += blockDim.x) dst[i] = src[i];
}

__global__ void xc_build() {
    int b = blockIdx.x, tid = threadIdx.x;
#pragma unroll
    for (int r = 0; r < 2; r++) {
        int j = tid + r * 256;
        g_xc[b][j]       = g_h[0][b][j];
        g_xc[b][512 + j] = g_h[1][b][j];
    }
}

__global__ void out_build(float* __restrict__ out) {
    int b = blockIdx.x, tid = threadIdx.x;
#pragma unroll
    for (int r = 0; r < 2; r++) {
        int j = tid + r * 256;
        out[(size_t)b * 1024 + j]       = g_h[0][b][j];
        out[(size_t)b * 1024 + 512 + j] = g_h[1][b][j];
    }
}

// ------------------------- block LN statistics -----------------------------
// 256-thread block reduce of (sum, sumsq) -> (mu, rsqrt(var+eps)).
// sm must hold >= 18 floats. Safe for back-to-back reuse (leading sync).
__device__ __forceinline__ float2 ln_stats(float s, float q, float n, float* sm) {
    __syncthreads();
#pragma unroll
    for (int o = 16; o; o >>= 1) {
        s += __shfl_xor_sync(0xffffffffu, s, o);
        q += __shfl_xor_sync(0xffffffffu, q, o);
    }
    int tid = threadIdx.x;
    if ((tid & 31) == 0) { sm[tid >> 5] = s; sm[(tid >> 5) + 8] = q; }
    __syncthreads();
    if (tid == 0) {
        float ts = 0.f, tq = 0.f;
#pragma unroll
        for (int w = 0; w < 8; w++) { ts += sm[w]; tq += sm[w + 8]; }
        float mu = ts / n;
        float var = tq / n - mu * mu;
        sm[16] = mu;
        sm[17] = rsqrtf(var + EPS);
    }
    __syncthreads();
    return make_float2(sm[16], sm[17]);
}

// ------------------------- row LayerNorm (in place) ------------------------
// data laid out [2][rowsPerDir][2048]; gamma/beta are [2][2048].
__global__ void ln_rows(int mode, const float* __restrict__ gamma,
                        const float* __restrict__ beta) {
    __shared__ float sm[32];
    int rows = mode ? Bz : Sz * Bz;
    int dir = blockIdx.y;
    float* row = (mode ? &g_G1[0][0][0] : &g_G0[0][0][0][0]) +
                 ((size_t)dir * rows + blockIdx.x) * Gz;
    int tid = threadIdx.x;

    float4 a = ((const float4*)row)[tid];
    float4 b = ((const float4*)row)[tid + 256];
    float s = a.x + a.y + a.z + a.w + b.x + b.y + b.z + b.w;
    float q = a.x * a.x + a.y * a.y + a.z * a.z + a.w * a.w +
              b.x * b.x + b.y * b.y + b.z * b.z + b.w * b.w;
    float2 st = ln_stats(s, q, (float)Gz, sm);

    const float* gg = gamma + (size_t)dir * Gz;
    const float* gb = beta + (size_t)dir * Gz;
    float4 gv = ((const float4*)gg)[tid];
    float4 bv = ((const float4*)gb)[tid];
    float4 o;
    o.x = (a.x - st.x) * st.y * gv.x + bv.x;
    o.y = (a.y - st.x) * st.y * gv.y + bv.y;
    o.z = (a.z - st.x) * st.y * gv.z + bv.z;
    o.w = (a.w - st.x) * st.y * gv.w + bv.w;
    ((float4*)row)[tid] = o;

    gv = ((const float4*)gg)[tid + 256];
    bv = ((const float4*)gb)[tid + 256];
    o.x = (b.x - st.x) * st.y * gv.x + bv.x;
    o.y = (b.y - st.x) * st.y * gv.y + bv.y;
    o.z = (b.z - st.x) * st.y * gv.z + bv.z;
    o.w = (b.w - st.x) * st.y * gv.w + bv.w;
    ((float4*)row)[tid + 256] = o;
}

// ------------------------- 64x64 fp32 GEMM tile core -----------------------
// C[64,64] (+)= A[64,klen] * W[64,klen]^T ; A,W row-major with given leading
// dims; 256 threads; BK=16; smem k-major with pad-to-68 (keeps LDS.128 aligned).
__device__ __forceinline__ void gemm64x64(const float* __restrict__ A, int lda,
                                          const float* __restrict__ W, int ldw,
                                          float* __restrict__ C, int ldc,
                                          int klen) {
    __shared__ float As[16][68];
    __shared__ float Ws[16][68];
    int t = threadIdx.x;
    int lm = t >> 2;           // 0..63
    int lk = (t & 3) << 2;     // 0,4,8,12
    int tx = t & 15, ty = t >> 4;

    float acc[4][4];
#pragma unroll
    for (int i = 0; i < 4; i++)
#pragma unroll
        for (int j = 0; j < 4; j++) acc[i][j] = 0.f;

    for (int k0 = 0; k0 < klen; k0 += 16) {
        float4 av = *(const float4*)(A + (size_t)lm * lda + k0 + lk);
        float4 wv = *(const float4*)(W + (size_t)lm * ldw + k0 + lk);
        __syncthreads();
        As[lk + 0][lm] = av.x; As[lk + 1][lm] = av.y;
        As[lk + 2][lm] = av.z; As[lk + 3][lm] = av.w;
        Ws[lk + 0][lm] = wv.x; Ws[lk + 1][lm] = wv.y;
        Ws[lk + 2][lm] = wv.z; Ws[lk + 3][lm] = wv.w;
        __syncthreads();
#pragma unroll
        for (int kk = 0; kk < 16; kk++) {
            float4 a = *(const float4*)&As[kk][ty << 2];
            float4 b = *(const float4*)&Ws[kk][tx << 2];
            acc[0][0] += a.x * b.x; acc[0][1] += a.x * b.y;
            acc[0][2] += a.x * b.z; acc[0][3] += a.x * b.w;
            acc[1][0] += a.y * b.x; acc[1][1] += a.y * b.y;
            acc[1][2] += a.y * b.z; acc[1][3] += a.y * b.w;
            acc[2][0] += a.z * b.x; acc[2][1] += a.z * b.y;
            acc[2][2] += a.z * b.z; acc[2][3] += a.z * b.w;
            acc[3][0] += a.w * b.x; acc[3][1] += a.w * b.y;
            acc[3][2] += a.w * b.z; acc[3][3] += a.w * b.w;
        }
    }
#pragma unroll
    for (int i = 0; i < 4; i++) {
        float4 v = make_float4(acc[i][0], acc[i][1], acc[i][2], acc[i][3]);
        *(float4*)(C + (size_t)((ty << 2) + i) * ldc + (tx << 2)) = v;
    }
}

// ------------------------- input projections -------------------------------
// mode 0: G0raw[dir] = xT @ w_ih0[dir]^T   (M=3072, K=512)
// mode 1: G1raw[dir] = xc @ w_ih1[dir]^T   (M=64,   K=1024)
__global__ void gemm_nt(const float* __restrict__ Wbase, int mode) {
    int m0 = blockIdx.x << 6;
    int n0 = blockIdx.y << 6;
    int dir = blockIdx.z;
    if (mode == 0) {
        const float* A = &g_xT[0][0] + (size_t)m0 * Ez;
        const float* W = Wbase + ((size_t)dir * Gz + n0) * Ez;
        float* C = &g_G0[dir][0][0][0] + (size_t)m0 * Gz + n0;
        gemm64x64(A, Ez, W, Ez, C, Gz, Ez);
    } else {
        const float* A = &g_xc[0][0] + (size_t)m0 * (2 * Hz);
        const float* W = Wbase + ((size_t)dir * Gz + n0) * (2 * Hz);
        float* C = &g_G1[dir][0][0] + (size_t)m0 * Gz + n0;
        gemm64x64(A, 2 * Hz, W, 2 * Hz, C, Gz, 2 * Hz);
    }
}

// ------------------------- recurrent step GEMM -----------------------------
// Yp[ks][dir][b][g] = sum_{h in ks-chunk} g_h[dir][b][h] * Whh[dir][g][h]
__global__ void step_gemm(const float* __restrict__ Whh) {
    int n0 = blockIdx.x << 6;     // 32 N-tiles
    int ks = blockIdx.y;          // split-K of 2, chunk 256
    int dir = blockIdx.z;
    const float* A = &g_h[dir][0][0] + ks * 256;
    const float* W = Whh + ((size_t)dir * Gz + n0) * Hz + ks * 256;
    float* C = &g_Yp[ks][dir][0][0] + n0;
    gemm64x64(A, Hz, W, Hz, C, Gz, 256);
}

// ------------------------- recurrent cell update ---------------------------
// One CTA per (b, dir): split-K reduce + LN(y) + gates + c + LN(c) + h.
__global__ void step_cell(int layer, int t,
                          const float* __restrict__ lnhh_g,
                          const float* __restrict__ lnhh_b,
                          const float* __restrict__ lnho_g,
                          const float* __restrict__ lnho_b) {
    __shared__ float sy[Gz];
    __shared__ float sm[32];
    int b = blockIdx.x, dir = blockIdx.y, tid = threadIdx.x;

    const float* gih;
    if (layer == 0) {
        int ts_ = dir ? (Sz - 1 - t) : t;
        gih = &g_G0[dir][ts_][b][0];
    } else {
        gih = &g_G1[dir][b][0];
    }

    // sum split-K partials, gather LN stats over 2048
    const float* y0 = &g_Yp[0][dir][b][0];
    const float* y1 = &g_Yp[1][dir][b][0];
    float s = 0.f, q = 0.f;
#pragma unroll
    for (int r = 0; r < 2; r++) {
        int i4 = tid + r * 256;      // float4 index, 512 total
        float4 p = ((const float4*)y0)[i4];
        float4 p1 = ((const float4*)y1)[i4];
        p.x += p1.x; p.y += p1.y; p.z += p1.z; p.w += p1.w;
        ((float4*)sy)[i4] = p;
        s += p.x + p.y + p.z + p.w;
        q += p.x * p.x + p.y * p.y + p.z * p.z + p.w * p.w;
    }
    float2 st = ln_stats(s, q, (float)Gz, sm);

    const float* gg = lnhh_g + (size_t)dir * Gz;
    const float* gb = lnhh_b + (size_t)dir * Gz;

    float o_[2], c_[2];
    float cs = 0.f, cq = 0.f;
#pragma unroll
    for (int r = 0; r < 2; r++) {
        int hh = tid + r * 256;     // 0..511
        float gi = gih[hh]        + (sy[hh]        - st.x) * st.y * gg[hh]        + gb[hh];
        float gf = gih[512 + hh]  + (sy[512 + hh]  - st.x) * st.y * gg[512 + hh]  + gb[512 + hh];
        float go = gih[1024 + hh] + (sy[1024 + hh] - st.x) * st.y * gg[1024 + hh] + gb[1024 + hh];
        float gz = gih[1536 + hh] + (sy[1536 + hh] - st.x) * st.y * gg[1536 + hh] + gb[1536 + hh];

        float ig = 1.f / (1.f + expf(-gi));
        float fg = 1.f / (1.f + expf(-gf));
        float og = 1.f / (1.f + expf(-go));
        float zg = tanhf(gz);

        float c = fg * g_c[dir][b][hh] + ig * zg;
        g_c[dir][b][hh] = c;
        o_[r] = og; c_[r] = c;
        cs += c; cq += c * c;
    }
    float2 st2 = ln_stats(cs, cq, (float)Hz, sm);

    const float* og_ = lnho_g + (size_t)dir * Hz;
    const float* ob_ = lnho_b + (size_t)dir * Hz;
#pragma unroll
    for (int r = 0; r < 2; r++) {
        int hh = tid + r * 256;
        float cn = (c_[r] - st2.x) * st2.y * og_[hh] + ob_[hh];
        g_h[dir][b][hh] = o_[r] * tanhf(cn);
    }
}

// ---------------------------------------------------------------------------
extern "C" void kernel_launch(void* const* d_in, const int* in_sizes, int n_in,
                              void* d_out, int out_size) {
    const float* x        = (const float*)d_in[0];
    // d_in[1] = text_length (unused by reference forward)
    const float* w_ih0    = (const float*)d_in[2];
    const float* w_hh0    = (const float*)d_in[3];
    const float* ln_ih0_g = (const float*)d_in[4];
    const float* ln_ih0_b = (const float*)d_in[5];
    const float* ln_hh0_g = (const float*)d_in[6];
    const float* ln_hh0_b = (const float*)d_in[7];
    const float* ln_ho0_g = (const float*)d_in[8];
    const float* ln_ho0_b = (const float*)d_in[9];
    const float* w_ih1    = (const float*)d_in[10];
    const float* w_hh1    = (const float*)d_in[11];
    const float* ln_ih1_g = (const float*)d_in[12];
    const float* ln_ih1_b = (const float*)d_in[13];
    const float* ln_hh1_g = (const float*)d_in[14];
    const float* ln_hh1_b = (const float*)d_in[15];
    const float* ln_ho1_g = (const float*)d_in[16];
    const float* ln_ho1_b = (const float*)d_in[17];
    float* out = (float*)d_out;

    // init states + layer-0 input projection (parallel part)
    zero_hc<<<256, 256>>>();
    transpose_x<<<Sz * Bz, 128>>>(x);
    gemm_nt<<<dim3(48, 32, 2), 256>>>(w_ih0, 0);
    ln_rows<<<dim3(Sz * Bz, 2), 256>>>(0, ln_ih0_g, ln_ih0_b);

    // layer-0 scan (forward dir0, backward dir1, run concurrently)
    for (int t = 0; t < Sz; t++) {
        step_gemm<<<dim3(32, 2, 2), 256>>>(w_hh0);
        step_cell<<<dim3(Bz, 2), 256>>>(0, t, ln_hh0_g, ln_hh0_b,
                                        ln_ho0_g, ln_ho0_b);
    }

    // layer-1 constant input (aliasing bug: same input every timestep)
    xc_build<<<Bz, 256>>>();
    gemm_nt<<<dim3(1, 32, 2), 256>>>(w_ih1, 1);
    ln_rows<<<dim3(Bz, 2), 256>>>(1, ln_ih1_g, ln_ih1_b);
    zero_hc<<<256, 256>>>();

    // layer-1 scan
    for (int t = 0; t < Sz; t++) {
        step_gemm<<<dim3(32, 2, 2), 256>>>(w_hh1);
        step_cell<<<dim3(Bz, 2), 256>>>(1, t, ln_hh1_g, ln_hh1_b,
                                        ln_ho1_g, ln_ho1_b);
    }

    out_build<<<Bz, 256>>>(out);
}